// round 11
// baseline (speedup 1.0000x reference)
#include <cuda_runtime.h>
#include <cuda_fp16.h>
#include <math.h>
#include <stdint.h>

#define FIN 128
#define HID 64
#define N_MAX 100032
#define LRELU_ALPHA 0.2f

// ---- scratch (static device globals; no allocation allowed) ----
__device__ __half2 g_fts_h[(size_t)N_MAX * 32];  // seq@W as fp16 [N,64] 12.8MB (L2-resident)
__device__ float   g_f1[N_MAX];
__device__ float   g_f2[N_MAX];
__device__ int     g_rowptr[N_MAX + 1];

#define XT_STRIDE 132   // floats per k-row of transposed X tile (16B-aligned rows)

// ============================================================================
// K1: seq_fts = seq @ W via packed fma.rn.f32x2 — EXACT R5 kernel (measured
//   56.2us). 128-node x 64-hid tile per 256-thread block; Xt transposed in
//   smem so A node-pairs are contiguous u64 (broadcast LDS.128).
//   Fused epilogue: f1/f2 dots + fp16 fts store.
// ============================================================================
__global__ void __launch_bounds__(256, 2)
gemm_f12_kernel(const float* __restrict__ seq, const float* __restrict__ W,
                const float* __restrict__ a1, const float* __restrict__ b1,
                const float* __restrict__ a2, const float* __restrict__ b2,
                int N) {
    extern __shared__ float sm[];
    float* Ws = sm;                       // [128][64]              32KB
    float* Xt = sm + FIN * HID;           // [128 k][132] transposed 66KB
    const int tid = threadIdx.x;
    const int n0 = blockIdx.x * 128;

    {
        const float4* W4 = (const float4*)W;
        float4* Ws4 = (float4*)Ws;
        #pragma unroll
        for (int i = tid; i < FIN * HID / 4; i += 256) Ws4[i] = W4[i];
    }
    for (int i = tid; i < 128 * 32; i += 256) {
        int node = i & 127;
        int kk4 = i >> 7;
        float4 v = make_float4(0.f, 0.f, 0.f, 0.f);
        if (n0 + node < N)
            v = ((const float4*)(seq + (size_t)(n0 + node) * FIN))[kk4];
        Xt[(kk4 * 4 + 0) * XT_STRIDE + node] = v.x;
        Xt[(kk4 * 4 + 1) * XT_STRIDE + node] = v.y;
        Xt[(kk4 * 4 + 2) * XT_STRIDE + node] = v.z;
        Xt[(kk4 * 4 + 3) * XT_STRIDE + node] = v.w;
    }
    __syncthreads();

    const int tx = tid & 15;   // hid group: cols [tx*4, tx*4+4)
    const int ty = tid >> 4;   // node group: nodes [ty*8, ty*8+8) as 4 pairs

    unsigned bAddr = (unsigned)__cvta_generic_to_shared(Ws + tx * 4);
    unsigned aAddr = (unsigned)__cvta_generic_to_shared(Xt + ty * 8);

    unsigned long long acc[4][4];
    #pragma unroll
    for (int p = 0; p < 4; p++)
        #pragma unroll
        for (int h = 0; h < 4; h++) acc[p][h] = 0ull;

    #pragma unroll 4
    for (int k = 0; k < FIN; k++) {
        unsigned long long a01, a23, a45, a67;
        unsigned ak = aAddr + (unsigned)(k * (XT_STRIDE * 4));
        asm volatile("ld.shared.v2.u64 {%0,%1}, [%2];"
                     : "=l"(a01), "=l"(a23) : "r"(ak));
        asm volatile("ld.shared.v2.u64 {%0,%1}, [%2];"
                     : "=l"(a45), "=l"(a67) : "r"(ak + 16));
        float4 b;
        asm volatile("ld.shared.v4.f32 {%0,%1,%2,%3}, [%4];"
                     : "=f"(b.x), "=f"(b.y), "=f"(b.z), "=f"(b.w)
                     : "r"(bAddr + (unsigned)(k * HID * 4)));
        unsigned long long bb0, bb1, bb2, bb3;
        asm("mov.b64 %0, {%1,%1};" : "=l"(bb0) : "f"(b.x));
        asm("mov.b64 %0, {%1,%1};" : "=l"(bb1) : "f"(b.y));
        asm("mov.b64 %0, {%1,%1};" : "=l"(bb2) : "f"(b.z));
        asm("mov.b64 %0, {%1,%1};" : "=l"(bb3) : "f"(b.w));
        asm("fma.rn.f32x2 %0,%1,%2,%0;" : "+l"(acc[0][0]) : "l"(a01), "l"(bb0));
        asm("fma.rn.f32x2 %0,%1,%2,%0;" : "+l"(acc[0][1]) : "l"(a01), "l"(bb1));
        asm("fma.rn.f32x2 %0,%1,%2,%0;" : "+l"(acc[0][2]) : "l"(a01), "l"(bb2));
        asm("fma.rn.f32x2 %0,%1,%2,%0;" : "+l"(acc[0][3]) : "l"(a01), "l"(bb3));
        asm("fma.rn.f32x2 %0,%1,%2,%0;" : "+l"(acc[1][0]) : "l"(a23), "l"(bb0));
        asm("fma.rn.f32x2 %0,%1,%2,%0;" : "+l"(acc[1][1]) : "l"(a23), "l"(bb1));
        asm("fma.rn.f32x2 %0,%1,%2,%0;" : "+l"(acc[1][2]) : "l"(a23), "l"(bb2));
        asm("fma.rn.f32x2 %0,%1,%2,%0;" : "+l"(acc[1][3]) : "l"(a23), "l"(bb3));
        asm("fma.rn.f32x2 %0,%1,%2,%0;" : "+l"(acc[2][0]) : "l"(a45), "l"(bb0));
        asm("fma.rn.f32x2 %0,%1,%2,%0;" : "+l"(acc[2][1]) : "l"(a45), "l"(bb1));
        asm("fma.rn.f32x2 %0,%1,%2,%0;" : "+l"(acc[2][2]) : "l"(a45), "l"(bb2));
        asm("fma.rn.f32x2 %0,%1,%2,%0;" : "+l"(acc[2][3]) : "l"(a45), "l"(bb3));
        asm("fma.rn.f32x2 %0,%1,%2,%0;" : "+l"(acc[3][0]) : "l"(a67), "l"(bb0));
        asm("fma.rn.f32x2 %0,%1,%2,%0;" : "+l"(acc[3][1]) : "l"(a67), "l"(bb1));
        asm("fma.rn.f32x2 %0,%1,%2,%0;" : "+l"(acc[3][2]) : "l"(a67), "l"(bb2));
        asm("fma.rn.f32x2 %0,%1,%2,%0;" : "+l"(acc[3][3]) : "l"(a67), "l"(bb3));
    }

    float af[8][4];
    #pragma unroll
    for (int p = 0; p < 4; p++)
        #pragma unroll
        for (int h = 0; h < 4; h++)
            asm("mov.b64 {%0,%1}, %2;"
                : "=f"(af[2 * p][h]), "=f"(af[2 * p + 1][h]) : "l"(acc[p][h]));

    #pragma unroll
    for (int i = 0; i < 8; i++) {
        int n = n0 + ty * 8 + i;
        if (n < N) {
            __half2 h0 = __floats2half2_rn(af[i][0], af[i][1]);
            __half2 h1 = __floats2half2_rn(af[i][2], af[i][3]);
            __half2* dst = g_fts_h + (size_t)n * 32 + tx * 2;
            dst[0] = h0;
            dst[1] = h1;
        }
    }

    float a1v0 = a1[tx * 4], a1v1 = a1[tx * 4 + 1], a1v2 = a1[tx * 4 + 2], a1v3 = a1[tx * 4 + 3];
    float a2v0 = a2[tx * 4], a2v1 = a2[tx * 4 + 1], a2v2 = a2[tx * 4 + 2], a2v3 = a2[tx * 4 + 3];
    float bb1s = b1[0], bb2s = b2[0];
    #pragma unroll
    for (int i = 0; i < 8; i++) {
        float p1 = af[i][0] * a1v0 + af[i][1] * a1v1 + af[i][2] * a1v2 + af[i][3] * a1v3;
        float p2 = af[i][0] * a2v0 + af[i][1] * a2v1 + af[i][2] * a2v2 + af[i][3] * a2v3;
        #pragma unroll
        for (int o = 8; o; o >>= 1) {
            p1 += __shfl_xor_sync(0xFFFFFFFFu, p1, o);
            p2 += __shfl_xor_sync(0xFFFFFFFFu, p2, o);
        }
        int n = n0 + ty * 8 + i;
        if (tx == 0 && n < N) {
            g_f1[n] = p1 + bb1s;
            g_f2[n] = p2 + bb2s;
        }
    }
}

// ============================================================================
// K2: CSR row_ptr from sorted edge_row
// ============================================================================
__global__ void build_rowptr(const int* __restrict__ erow, int E, int N) {
    int e = blockIdx.x * blockDim.x + threadIdx.x;
    if (e >= E) return;
    int r = erow[e];
    int rp = (e == 0) ? -1 : erow[e - 1];
    for (int rr = rp + 1; rr <= r; ++rr) g_rowptr[rr] = e;
    if (e == E - 1)
        for (int rr = r + 1; rr <= N; ++rr) g_rowptr[rr] = E;
}

// ============================================================================
// K3: fused logits + segmented softmax + SpMM + ELU. One warp per row.
//   NEW: shuffle-free gather. After the 32-lane z-phase, (c,z) pairs are
//   stashed in a per-warp smem buffer; the gather runs 4 edges/step with
//   8 lanes x 16B (uint4) per edge — broadcast LDS.64 for (c,z) (address is
//   static -> all 8 LDG.128 steps independent, MLP~8), zero shuffles.
// ============================================================================
__global__ void __launch_bounds__(256)
attn_kernel(const int* __restrict__ ec, const float* __restrict__ ev,
            float* __restrict__ out, int N) {
    __shared__ uint2 sbuf[8][32];     // per-warp (c,z) staging, 2KB

    const int warp = threadIdx.x >> 5;
    const int lane = threadIdx.x & 31;
    int row = blockIdx.x * 8 + warp;
    if (row >= N) return;

    const int s = g_rowptr[row];
    const int e = g_rowptr[row + 1];
    const float f1r = g_f1[row];

    const int eg = lane >> 3;   // edge-group 0..3 (which edge of 4 this lane serves)
    const int li = lane & 7;    // 16B slice within the 64-half row

    float acc[8];
    #pragma unroll
    for (int i = 0; i < 8; i++) acc[i] = 0.f;
    float ssum = 0.f;

    for (int base = s; base < e; base += 32) {
        // ---- z-phase: one edge per lane ----
        int idx = base + lane;
        float z = 0.f;
        int c = 0;
        if (idx < e) {
            c = ec[idx];
            float l = ev[idx] * (f1r + g_f2[c]);
            l = fmaxf(l, LRELU_ALPHA * l);      // leaky relu
            z = __expf(l);                      // shift-free softmax (logits O(10))
        }
        ssum += z;
        sbuf[warp][lane] = make_uint2((unsigned)c, __float_as_uint(z));
        __syncwarp();

        // ---- gather phase: 4 edges per step, no shuffles ----
        int cnt = min(32, e - base);
        if (cnt == 32) {
            #pragma unroll
            for (int j = 0; j < 8; j++) {
                uint2 cz = sbuf[warp][j * 4 + eg];
                float zz = __uint_as_float(cz.y);
                const uint4 r = *(const uint4*)(g_fts_h + (size_t)cz.x * 32 + li * 4);
                float2 v0 = __half22float2(*(__half2*)&r.x);
                float2 v1 = __half22float2(*(__half2*)&r.y);
                float2 v2 = __half22float2(*(__half2*)&r.z);
                float2 v3 = __half22float2(*(__half2*)&r.w);
                acc[0] += zz * v0.x; acc[1] += zz * v0.y;
                acc[2] += zz * v1.x; acc[3] += zz * v1.y;
                acc[4] += zz * v2.x; acc[5] += zz * v2.y;
                acc[6] += zz * v3.x; acc[7] += zz * v3.y;
            }
        } else {
            int steps = (cnt + 3) >> 2;          // padded lanes carry z=0,c=0
            for (int j = 0; j < steps; j++) {
                uint2 cz = sbuf[warp][j * 4 + eg];
                float zz = __uint_as_float(cz.y);
                const uint4 r = *(const uint4*)(g_fts_h + (size_t)cz.x * 32 + li * 4);
                float2 v0 = __half22float2(*(__half2*)&r.x);
                float2 v1 = __half22float2(*(__half2*)&r.y);
                float2 v2 = __half22float2(*(__half2*)&r.z);
                float2 v3 = __half22float2(*(__half2*)&r.w);
                acc[0] += zz * v0.x; acc[1] += zz * v0.y;
                acc[2] += zz * v1.x; acc[3] += zz * v1.y;
                acc[4] += zz * v2.x; acc[5] += zz * v2.y;
                acc[6] += zz * v3.x; acc[7] += zz * v3.y;
            }
        }
        __syncwarp();   // protect sbuf before next chunk overwrites
    }

    // ---- combine the 4 edge-groups (lanes sharing li) ----
    #pragma unroll
    for (int o = 8; o <= 16; o <<= 1)
        #pragma unroll
        for (int i = 0; i < 8; i++)
            acc[i] += __shfl_xor_sync(0xFFFFFFFFu, acc[i], o);
    #pragma unroll
    for (int o = 16; o; o >>= 1) ssum += __shfl_xor_sync(0xFFFFFFFFu, ssum, o);

    if (eg == 0) {
        float inv = (e > s) ? (1.f / ssum) : 0.f;
        float o8[8];
        #pragma unroll
        for (int i = 0; i < 8; i++) {
            float v = acc[i] * inv;
            o8[i] = v > 0.f ? v : expm1f(v);    // ELU
        }
        float* dst = out + (size_t)row * HID + li * 8;
        *(float4*)(dst)     = make_float4(o8[0], o8[1], o8[2], o8[3]);
        *(float4*)(dst + 4) = make_float4(o8[4], o8[5], o8[6], o8[7]);
    }
}

// ============================================================================
// launch
// ============================================================================
extern "C" void kernel_launch(void* const* d_in, const int* in_sizes, int n_in,
                              void* d_out, int out_size) {
    const float* seq = (const float*)d_in[0];
    const int*   er  = (const int*)d_in[1];
    const int*   ec  = (const int*)d_in[2];
    const float* ev  = (const float*)d_in[3];
    const float* W   = (const float*)d_in[4];
    const float* a1  = (const float*)d_in[5];
    const float* b1  = (const float*)d_in[6];
    const float* a2  = (const float*)d_in[7];
    const float* b2  = (const float*)d_in[8];
    // d_in[9] = bias_zero (all zeros — no-op)
    float* out = (float*)d_out;

    int N = in_sizes[0] / FIN;   // seq is [1, N, 128]
    int E = in_sizes[1];

    const int SMEM = (FIN * HID + FIN * XT_STRIDE) * (int)sizeof(float);  // ~98KB
    cudaFuncSetAttribute(gemm_f12_kernel,
                         cudaFuncAttributeMaxDynamicSharedMemorySize, SMEM);

    gemm_f12_kernel<<<(N + 127) / 128, 256, SMEM>>>(seq, W, a1, b1, a2, b2, N);
    build_rowptr<<<(E + 255) / 256, 256>>>(er, E, N);
    attn_kernel<<<(N + 7) / 8, 256>>>(ec, ev, out, N);
}

// round 12
// speedup vs baseline: 1.4290x; 1.4290x over previous
#include <cuda_runtime.h>
#include <cuda_fp16.h>
#include <math.h>
#include <stdint.h>

#define FIN 128
#define HID 64
#define N_MAX 100032
#define LRELU_ALPHA 0.2f

// ---- scratch (static device globals; no allocation allowed) ----
__device__ __half2 g_fts_h[(size_t)N_MAX * 32];  // seq@W as fp16 [N,64] 12.8MB (L2-resident)
__device__ float   g_f1[N_MAX];
__device__ float   g_f2[N_MAX];
__device__ int     g_rowptr[N_MAX + 1];

#define XT_STRIDE 132   // floats per k-row of transposed X tile
#define KSTAGE    64    // k rows resident per stage

// ============================================================================
// K1: seq_fts = seq @ W via packed fma.rn.f32x2 (FFMA2).
//   R5's clean inner loop (no manual prefetch rotation), but K split into two
//   64-row stages so smem = 32KB (Ws) + 33KB (Xt) = 65KB -> 3 CTAs/SM
//   (6 warps/SMSP to hide the 29-cyc LDS). Fused f1/f2 + fp16 fts epilogue.
// ============================================================================
__global__ void __launch_bounds__(256, 3)
gemm_f12_kernel(const float* __restrict__ seq, const float* __restrict__ W,
                const float* __restrict__ a1, const float* __restrict__ b1,
                const float* __restrict__ a2, const float* __restrict__ b2,
                int N) {
    extern __shared__ float sm[];
    float* Ws = sm;                       // [128][64]            32KB (full K)
    float* Xt = sm + FIN * HID;           // [64][132] transposed 33KB (half K)
    const int tid = threadIdx.x;
    const int n0 = blockIdx.x * 128;

    {
        const float4* W4 = (const float4*)W;
        float4* Ws4 = (float4*)Ws;
        #pragma unroll
        for (int i = tid; i < FIN * HID / 4; i += 256) Ws4[i] = W4[i];
    }

    const int tx = tid & 15;   // hid group: cols [tx*4, tx*4+4)
    const int ty = tid >> 4;   // node group: nodes [ty*8, ty*8+8) as 4 pairs

    unsigned bAddr = (unsigned)__cvta_generic_to_shared(Ws + tx * 4);
    unsigned aAddr = (unsigned)__cvta_generic_to_shared(Xt + ty * 8);

    unsigned long long acc[4][4];
    #pragma unroll
    for (int p = 0; p < 4; p++)
        #pragma unroll
        for (int h = 0; h < 4; h++) acc[p][h] = 0ull;

    for (int stage = 0; stage < 2; stage++) {
        __syncthreads();
        // load this stage's 64 k-rows of X, transposed
        for (int i = tid; i < 128 * 16; i += 256) {
            int node = i & 127;
            int q = i >> 7;                 // 0..15
            int kk4 = stage * 16 + q;       // float4 index in the 128-f row
            float4 v = make_float4(0.f, 0.f, 0.f, 0.f);
            if (n0 + node < N)
                v = ((const float4*)(seq + (size_t)(n0 + node) * FIN))[kk4];
            Xt[(q * 4 + 0) * XT_STRIDE + node] = v.x;
            Xt[(q * 4 + 1) * XT_STRIDE + node] = v.y;
            Xt[(q * 4 + 2) * XT_STRIDE + node] = v.z;
            Xt[(q * 4 + 3) * XT_STRIDE + node] = v.w;
        }
        __syncthreads();

        const unsigned bBase = bAddr + (unsigned)(stage * KSTAGE * HID * 4);

        #pragma unroll 4
        for (int k = 0; k < KSTAGE; k++) {
            unsigned long long a01, a23, a45, a67;
            unsigned ak = aAddr + (unsigned)(k * (XT_STRIDE * 4));
            asm volatile("ld.shared.v2.u64 {%0,%1}, [%2];"
                         : "=l"(a01), "=l"(a23) : "r"(ak));
            asm volatile("ld.shared.v2.u64 {%0,%1}, [%2];"
                         : "=l"(a45), "=l"(a67) : "r"(ak + 16));
            float4 b;
            asm volatile("ld.shared.v4.f32 {%0,%1,%2,%3}, [%4];"
                         : "=f"(b.x), "=f"(b.y), "=f"(b.z), "=f"(b.w)
                         : "r"(bBase + (unsigned)(k * HID * 4)));
            unsigned long long bb0, bb1, bb2, bb3;
            asm("mov.b64 %0, {%1,%1};" : "=l"(bb0) : "f"(b.x));
            asm("mov.b64 %0, {%1,%1};" : "=l"(bb1) : "f"(b.y));
            asm("mov.b64 %0, {%1,%1};" : "=l"(bb2) : "f"(b.z));
            asm("mov.b64 %0, {%1,%1};" : "=l"(bb3) : "f"(b.w));
            asm("fma.rn.f32x2 %0,%1,%2,%0;" : "+l"(acc[0][0]) : "l"(a01), "l"(bb0));
            asm("fma.rn.f32x2 %0,%1,%2,%0;" : "+l"(acc[0][1]) : "l"(a01), "l"(bb1));
            asm("fma.rn.f32x2 %0,%1,%2,%0;" : "+l"(acc[0][2]) : "l"(a01), "l"(bb2));
            asm("fma.rn.f32x2 %0,%1,%2,%0;" : "+l"(acc[0][3]) : "l"(a01), "l"(bb3));
            asm("fma.rn.f32x2 %0,%1,%2,%0;" : "+l"(acc[1][0]) : "l"(a23), "l"(bb0));
            asm("fma.rn.f32x2 %0,%1,%2,%0;" : "+l"(acc[1][1]) : "l"(a23), "l"(bb1));
            asm("fma.rn.f32x2 %0,%1,%2,%0;" : "+l"(acc[1][2]) : "l"(a23), "l"(bb2));
            asm("fma.rn.f32x2 %0,%1,%2,%0;" : "+l"(acc[1][3]) : "l"(a23), "l"(bb3));
            asm("fma.rn.f32x2 %0,%1,%2,%0;" : "+l"(acc[2][0]) : "l"(a45), "l"(bb0));
            asm("fma.rn.f32x2 %0,%1,%2,%0;" : "+l"(acc[2][1]) : "l"(a45), "l"(bb1));
            asm("fma.rn.f32x2 %0,%1,%2,%0;" : "+l"(acc[2][2]) : "l"(a45), "l"(bb2));
            asm("fma.rn.f32x2 %0,%1,%2,%0;" : "+l"(acc[2][3]) : "l"(a45), "l"(bb3));
            asm("fma.rn.f32x2 %0,%1,%2,%0;" : "+l"(acc[3][0]) : "l"(a67), "l"(bb0));
            asm("fma.rn.f32x2 %0,%1,%2,%0;" : "+l"(acc[3][1]) : "l"(a67), "l"(bb1));
            asm("fma.rn.f32x2 %0,%1,%2,%0;" : "+l"(acc[3][2]) : "l"(a67), "l"(bb2));
            asm("fma.rn.f32x2 %0,%1,%2,%0;" : "+l"(acc[3][3]) : "l"(a67), "l"(bb3));
        }
    }

    float af[8][4];
    #pragma unroll
    for (int p = 0; p < 4; p++)
        #pragma unroll
        for (int h = 0; h < 4; h++)
            asm("mov.b64 {%0,%1}, %2;"
                : "=f"(af[2 * p][h]), "=f"(af[2 * p + 1][h]) : "l"(acc[p][h]));

    #pragma unroll
    for (int i = 0; i < 8; i++) {
        int n = n0 + ty * 8 + i;
        if (n < N) {
            __half2 h0 = __floats2half2_rn(af[i][0], af[i][1]);
            __half2 h1 = __floats2half2_rn(af[i][2], af[i][3]);
            __half2* dst = g_fts_h + (size_t)n * 32 + tx * 2;
            dst[0] = h0;
            dst[1] = h1;
        }
    }

    float a1v0 = a1[tx * 4], a1v1 = a1[tx * 4 + 1], a1v2 = a1[tx * 4 + 2], a1v3 = a1[tx * 4 + 3];
    float a2v0 = a2[tx * 4], a2v1 = a2[tx * 4 + 1], a2v2 = a2[tx * 4 + 2], a2v3 = a2[tx * 4 + 3];
    float bb1s = b1[0], bb2s = b2[0];
    #pragma unroll
    for (int i = 0; i < 8; i++) {
        float p1 = af[i][0] * a1v0 + af[i][1] * a1v1 + af[i][2] * a1v2 + af[i][3] * a1v3;
        float p2 = af[i][0] * a2v0 + af[i][1] * a2v1 + af[i][2] * a2v2 + af[i][3] * a2v3;
        #pragma unroll
        for (int o = 8; o; o >>= 1) {
            p1 += __shfl_xor_sync(0xFFFFFFFFu, p1, o);
            p2 += __shfl_xor_sync(0xFFFFFFFFu, p2, o);
        }
        int n = n0 + ty * 8 + i;
        if (tx == 0 && n < N) {
            g_f1[n] = p1 + bb1s;
            g_f2[n] = p2 + bb2s;
        }
    }
}

// ============================================================================
// K2: CSR row_ptr from sorted edge_row
// ============================================================================
__global__ void build_rowptr(const int* __restrict__ erow, int E, int N) {
    int e = blockIdx.x * blockDim.x + threadIdx.x;
    if (e >= E) return;
    int r = erow[e];
    int rp = (e == 0) ? -1 : erow[e - 1];
    for (int rr = rp + 1; rr <= r; ++rr) g_rowptr[rr] = e;
    if (e == E - 1)
        for (int rr = r + 1; rr <= N; ++rr) g_rowptr[rr] = E;
}

// ============================================================================
// K3: fused logits + segmented softmax + SpMM + ELU.
//   TWO warps per row (interleaved 32-edge chunks) -> halves the per-row
//   serial z->gather chain and doubles outstanding gather parallelism.
//   Partials (8 floats/lane on eg==0 lanes + ssum) combined via smem.
// ============================================================================
__global__ void __launch_bounds__(256)
attn_kernel(const int* __restrict__ ec, const float* __restrict__ ev,
            float* __restrict__ out, int N) {
    __shared__ uint2 sbuf[8][32];          // per-warp (c,z) staging
    __shared__ float sacc[4][2][8][8];     // [row-in-block][halfwarp][li][h]
    __shared__ float ssums[4][2];

    const int warp = threadIdx.x >> 5;
    const int lane = threadIdx.x & 31;
    const int rloc = warp >> 1;            // row within block (0..3)
    const int hw   = warp & 1;             // which half-warp-team
    int row = blockIdx.x * 4 + rloc;
    const bool active = (row < N);

    int s = 0, e = 0;
    float f1r = 0.f;
    if (active) {
        s = g_rowptr[row];
        e = g_rowptr[row + 1];
        f1r = g_f1[row];
    }

    const int eg = lane >> 3;   // edge-group 0..3
    const int li = lane & 7;    // 16B slice of the 128B feature row

    float acc[8];
    #pragma unroll
    for (int i = 0; i < 8; i++) acc[i] = 0.f;
    float ssum = 0.f;

    if (active) {
        for (int base = s + hw * 32; base < e; base += 64) {
            // ---- z-phase: one edge per lane ----
            int idx = base + lane;
            float z = 0.f;
            int c = 0;
            if (idx < e) {
                c = ec[idx];
                float l = ev[idx] * (f1r + g_f2[c]);
                l = fmaxf(l, LRELU_ALPHA * l);
                z = __expf(l);              // shift-free softmax (logits O(10))
            }
            ssum += z;
            sbuf[warp][lane] = make_uint2((unsigned)c, __float_as_uint(z));
            __syncwarp();

            // ---- gather: 4 edges/step, 8 lanes x 16B each, no shuffles ----
            int cnt = min(32, e - base);
            if (cnt == 32) {
                #pragma unroll
                for (int j = 0; j < 8; j++) {
                    uint2 cz = sbuf[warp][j * 4 + eg];
                    float zz = __uint_as_float(cz.y);
                    const uint4 r = *(const uint4*)(g_fts_h + (size_t)cz.x * 32 + li * 4);
                    float2 v0 = __half22float2(*(__half2*)&r.x);
                    float2 v1 = __half22float2(*(__half2*)&r.y);
                    float2 v2 = __half22float2(*(__half2*)&r.z);
                    float2 v3 = __half22float2(*(__half2*)&r.w);
                    acc[0] += zz * v0.x; acc[1] += zz * v0.y;
                    acc[2] += zz * v1.x; acc[3] += zz * v1.y;
                    acc[4] += zz * v2.x; acc[5] += zz * v2.y;
                    acc[6] += zz * v3.x; acc[7] += zz * v3.y;
                }
            } else {
                int steps = (cnt + 3) >> 2;     // padded lanes carry z=0,c=0
                for (int j = 0; j < steps; j++) {
                    uint2 cz = sbuf[warp][j * 4 + eg];
                    float zz = __uint_as_float(cz.y);
                    const uint4 r = *(const uint4*)(g_fts_h + (size_t)cz.x * 32 + li * 4);
                    float2 v0 = __half22float2(*(__half2*)&r.x);
                    float2 v1 = __half22float2(*(__half2*)&r.y);
                    float2 v2 = __half22float2(*(__half2*)&r.z);
                    float2 v3 = __half22float2(*(__half2*)&r.w);
                    acc[0] += zz * v0.x; acc[1] += zz * v0.y;
                    acc[2] += zz * v1.x; acc[3] += zz * v1.y;
                    acc[4] += zz * v2.x; acc[5] += zz * v2.y;
                    acc[6] += zz * v3.x; acc[7] += zz * v3.y;
                }
            }
            __syncwarp();
        }
    }

    // warp-internal: fold the 4 edge-groups down to eg==0 lanes
    #pragma unroll
    for (int o = 8; o <= 16; o <<= 1)
        #pragma unroll
        for (int i = 0; i < 8; i++)
            acc[i] += __shfl_xor_sync(0xFFFFFFFFu, acc[i], o);
    #pragma unroll
    for (int o = 16; o; o >>= 1) ssum += __shfl_xor_sync(0xFFFFFFFFu, ssum, o);

    if (eg == 0) {
        #pragma unroll
        for (int j = 0; j < 8; j++) sacc[rloc][hw][li][j] = acc[j];
        if (li == 0) ssums[rloc][hw] = ssum;
    }
    __syncthreads();

    // combine the two warps' partials; hw==0 warp writes the output
    if (active && hw == 0 && eg == 0) {
        float tot = ssums[rloc][0] + ssums[rloc][1];
        float inv = (e > s) ? (1.f / tot) : 0.f;
        float o8[8];
        #pragma unroll
        for (int j = 0; j < 8; j++) {
            float v = (sacc[rloc][0][li][j] + sacc[rloc][1][li][j]) * inv;
            o8[j] = v > 0.f ? v : expm1f(v);    // ELU
        }
        float* dst = out + (size_t)row * HID + li * 8;
        *(float4*)(dst)     = make_float4(o8[0], o8[1], o8[2], o8[3]);
        *(float4*)(dst + 4) = make_float4(o8[4], o8[5], o8[6], o8[7]);
    }
}

// ============================================================================
// launch
// ============================================================================
extern "C" void kernel_launch(void* const* d_in, const int* in_sizes, int n_in,
                              void* d_out, int out_size) {
    const float* seq = (const float*)d_in[0];
    const int*   er  = (const int*)d_in[1];
    const int*   ec  = (const int*)d_in[2];
    const float* ev  = (const float*)d_in[3];
    const float* W   = (const float*)d_in[4];
    const float* a1  = (const float*)d_in[5];
    const float* b1  = (const float*)d_in[6];
    const float* a2  = (const float*)d_in[7];
    const float* b2  = (const float*)d_in[8];
    // d_in[9] = bias_zero (all zeros — no-op)
    float* out = (float*)d_out;

    int N = in_sizes[0] / FIN;   // seq is [1, N, 128]
    int E = in_sizes[1];

    const int SMEM = (FIN * HID + KSTAGE * XT_STRIDE) * (int)sizeof(float);  // ~65KB
    cudaFuncSetAttribute(gemm_f12_kernel,
                         cudaFuncAttributeMaxDynamicSharedMemorySize, SMEM);

    gemm_f12_kernel<<<(N + 127) / 128, 256, SMEM>>>(seq, W, a1, b1, a2, b2, N);
    build_rowptr<<<(E + 255) / 256, 256>>>(er, E, N);
    attn_kernel<<<(N + 3) / 4, 256>>>(ec, ev, out, N);
}

// round 13
// speedup vs baseline: 1.5638x; 1.0943x over previous
#include <cuda_runtime.h>
#include <cuda_fp16.h>
#include <math.h>
#include <stdint.h>

#define FIN 128
#define HID 64
#define N_MAX 100032
#define LRELU_ALPHA 0.2f

// ---- scratch (static device globals; no allocation allowed) ----
__device__ __half2 g_fts_h[(size_t)N_MAX * 32];  // seq@W as fp16 [N,64] 12.8MB (L2-resident)
__device__ float   g_f1[N_MAX];
__device__ float   g_f2[N_MAX];
__device__ int     g_rowptr[N_MAX + 1];

#define XT_STRIDE 132   // floats per k-row of transposed X tile
#define KSTAGE    64    // k rows resident per stage

// ============================================================================
// K1: seq_fts = seq @ W via packed fma.rn.f32x2 (FFMA2) — R12 version
//   (measured 55.2us full-clock). Two-stage Xt -> 65KB smem -> 3 CTAs/SM.
//   Fused epilogue: f1/f2 dots + fp16 fts store.
// ============================================================================
__global__ void __launch_bounds__(256, 3)
gemm_f12_kernel(const float* __restrict__ seq, const float* __restrict__ W,
                const float* __restrict__ a1, const float* __restrict__ b1,
                const float* __restrict__ a2, const float* __restrict__ b2,
                int N) {
    extern __shared__ float sm[];
    float* Ws = sm;                       // [128][64]            32KB (full K)
    float* Xt = sm + FIN * HID;           // [64][132] transposed 33KB (half K)
    const int tid = threadIdx.x;
    const int n0 = blockIdx.x * 128;

    {
        const float4* W4 = (const float4*)W;
        float4* Ws4 = (float4*)Ws;
        #pragma unroll
        for (int i = tid; i < FIN * HID / 4; i += 256) Ws4[i] = W4[i];
    }

    const int tx = tid & 15;   // hid group: cols [tx*4, tx*4+4)
    const int ty = tid >> 4;   // node group: nodes [ty*8, ty*8+8) as 4 pairs

    unsigned bAddr = (unsigned)__cvta_generic_to_shared(Ws + tx * 4);
    unsigned aAddr = (unsigned)__cvta_generic_to_shared(Xt + ty * 8);

    unsigned long long acc[4][4];
    #pragma unroll
    for (int p = 0; p < 4; p++)
        #pragma unroll
        for (int h = 0; h < 4; h++) acc[p][h] = 0ull;

    for (int stage = 0; stage < 2; stage++) {
        __syncthreads();
        for (int i = tid; i < 128 * 16; i += 256) {
            int node = i & 127;
            int q = i >> 7;
            int kk4 = stage * 16 + q;
            float4 v = make_float4(0.f, 0.f, 0.f, 0.f);
            if (n0 + node < N)
                v = ((const float4*)(seq + (size_t)(n0 + node) * FIN))[kk4];
            Xt[(q * 4 + 0) * XT_STRIDE + node] = v.x;
            Xt[(q * 4 + 1) * XT_STRIDE + node] = v.y;
            Xt[(q * 4 + 2) * XT_STRIDE + node] = v.z;
            Xt[(q * 4 + 3) * XT_STRIDE + node] = v.w;
        }
        __syncthreads();

        const unsigned bBase = bAddr + (unsigned)(stage * KSTAGE * HID * 4);

        #pragma unroll 4
        for (int k = 0; k < KSTAGE; k++) {
            unsigned long long a01, a23, a45, a67;
            unsigned ak = aAddr + (unsigned)(k * (XT_STRIDE * 4));
            asm volatile("ld.shared.v2.u64 {%0,%1}, [%2];"
                         : "=l"(a01), "=l"(a23) : "r"(ak));
            asm volatile("ld.shared.v2.u64 {%0,%1}, [%2];"
                         : "=l"(a45), "=l"(a67) : "r"(ak + 16));
            float4 b;
            asm volatile("ld.shared.v4.f32 {%0,%1,%2,%3}, [%4];"
                         : "=f"(b.x), "=f"(b.y), "=f"(b.z), "=f"(b.w)
                         : "r"(bBase + (unsigned)(k * HID * 4)));
            unsigned long long bb0, bb1, bb2, bb3;
            asm("mov.b64 %0, {%1,%1};" : "=l"(bb0) : "f"(b.x));
            asm("mov.b64 %0, {%1,%1};" : "=l"(bb1) : "f"(b.y));
            asm("mov.b64 %0, {%1,%1};" : "=l"(bb2) : "f"(b.z));
            asm("mov.b64 %0, {%1,%1};" : "=l"(bb3) : "f"(b.w));
            asm("fma.rn.f32x2 %0,%1,%2,%0;" : "+l"(acc[0][0]) : "l"(a01), "l"(bb0));
            asm("fma.rn.f32x2 %0,%1,%2,%0;" : "+l"(acc[0][1]) : "l"(a01), "l"(bb1));
            asm("fma.rn.f32x2 %0,%1,%2,%0;" : "+l"(acc[0][2]) : "l"(a01), "l"(bb2));
            asm("fma.rn.f32x2 %0,%1,%2,%0;" : "+l"(acc[0][3]) : "l"(a01), "l"(bb3));
            asm("fma.rn.f32x2 %0,%1,%2,%0;" : "+l"(acc[1][0]) : "l"(a23), "l"(bb0));
            asm("fma.rn.f32x2 %0,%1,%2,%0;" : "+l"(acc[1][1]) : "l"(a23), "l"(bb1));
            asm("fma.rn.f32x2 %0,%1,%2,%0;" : "+l"(acc[1][2]) : "l"(a23), "l"(bb2));
            asm("fma.rn.f32x2 %0,%1,%2,%0;" : "+l"(acc[1][3]) : "l"(a23), "l"(bb3));
            asm("fma.rn.f32x2 %0,%1,%2,%0;" : "+l"(acc[2][0]) : "l"(a45), "l"(bb0));
            asm("fma.rn.f32x2 %0,%1,%2,%0;" : "+l"(acc[2][1]) : "l"(a45), "l"(bb1));
            asm("fma.rn.f32x2 %0,%1,%2,%0;" : "+l"(acc[2][2]) : "l"(a45), "l"(bb2));
            asm("fma.rn.f32x2 %0,%1,%2,%0;" : "+l"(acc[2][3]) : "l"(a45), "l"(bb3));
            asm("fma.rn.f32x2 %0,%1,%2,%0;" : "+l"(acc[3][0]) : "l"(a67), "l"(bb0));
            asm("fma.rn.f32x2 %0,%1,%2,%0;" : "+l"(acc[3][1]) : "l"(a67), "l"(bb1));
            asm("fma.rn.f32x2 %0,%1,%2,%0;" : "+l"(acc[3][2]) : "l"(a67), "l"(bb2));
            asm("fma.rn.f32x2 %0,%1,%2,%0;" : "+l"(acc[3][3]) : "l"(a67), "l"(bb3));
        }
    }

    float af[8][4];
    #pragma unroll
    for (int p = 0; p < 4; p++)
        #pragma unroll
        for (int h = 0; h < 4; h++)
            asm("mov.b64 {%0,%1}, %2;"
                : "=f"(af[2 * p][h]), "=f"(af[2 * p + 1][h]) : "l"(acc[p][h]));

    #pragma unroll
    for (int i = 0; i < 8; i++) {
        int n = n0 + ty * 8 + i;
        if (n < N) {
            __half2 h0 = __floats2half2_rn(af[i][0], af[i][1]);
            __half2 h1 = __floats2half2_rn(af[i][2], af[i][3]);
            __half2* dst = g_fts_h + (size_t)n * 32 + tx * 2;
            dst[0] = h0;
            dst[1] = h1;
        }
    }

    float a1v0 = a1[tx * 4], a1v1 = a1[tx * 4 + 1], a1v2 = a1[tx * 4 + 2], a1v3 = a1[tx * 4 + 3];
    float a2v0 = a2[tx * 4], a2v1 = a2[tx * 4 + 1], a2v2 = a2[tx * 4 + 2], a2v3 = a2[tx * 4 + 3];
    float bb1s = b1[0], bb2s = b2[0];
    #pragma unroll
    for (int i = 0; i < 8; i++) {
        float p1 = af[i][0] * a1v0 + af[i][1] * a1v1 + af[i][2] * a1v2 + af[i][3] * a1v3;
        float p2 = af[i][0] * a2v0 + af[i][1] * a2v1 + af[i][2] * a2v2 + af[i][3] * a2v3;
        #pragma unroll
        for (int o = 8; o; o >>= 1) {
            p1 += __shfl_xor_sync(0xFFFFFFFFu, p1, o);
            p2 += __shfl_xor_sync(0xFFFFFFFFu, p2, o);
        }
        int n = n0 + ty * 8 + i;
        if (tx == 0 && n < N) {
            g_f1[n] = p1 + bb1s;
            g_f2[n] = p2 + bb2s;
        }
    }
}

// ============================================================================
// K2: CSR row_ptr from sorted edge_row
// ============================================================================
__global__ void build_rowptr(const int* __restrict__ erow, int E, int N) {
    int e = blockIdx.x * blockDim.x + threadIdx.x;
    if (e >= E) return;
    int r = erow[e];
    int rp = (e == 0) ? -1 : erow[e - 1];
    for (int rr = rp + 1; rr <= r; ++rr) g_rowptr[rr] = e;
    if (e == E - 1)
        for (int rr = r + 1; rr <= N; ++rr) g_rowptr[rr] = E;
}

// ============================================================================
// K3: fused logits + segmented softmax + SpMM + ELU.
//   R5's proven warp-level machinery, but each warp now owns TWO independent
//   rows (A,B) processed interleaved — the two per-row serial latency chains
//   (ec/ev -> f2 gather -> exp -> shfl -> feature gather) overlap, doubling
//   per-warp outstanding memory. No cross-warp combine, no extra syncs.
// ============================================================================
__device__ __forceinline__ void gather_chunk(int cnt, int half, int li,
                                             int c, float z,
                                             float4& acc0, float4& acc1) {
    int j = 0;
    for (; j + 2 < cnt; j += 4) {
        int s0 = j + half;
        int s1 = j + 2 + half;
        int   c0 = __shfl_sync(0xFFFFFFFFu, c, s0);
        float z0 = __shfl_sync(0xFFFFFFFFu, z, s0);
        int   c1 = __shfl_sync(0xFFFFFFFFu, c, s1);
        float z1 = __shfl_sync(0xFFFFFFFFu, z, s1);
        uint2 r0 = *(const uint2*)(g_fts_h + (size_t)c0 * 32 + li * 2);
        uint2 r1 = *(const uint2*)(g_fts_h + (size_t)c1 * 32 + li * 2);
        float2 v00 = __half22float2(*(__half2*)&r0.x);
        float2 v01 = __half22float2(*(__half2*)&r0.y);
        float2 v10 = __half22float2(*(__half2*)&r1.x);
        float2 v11 = __half22float2(*(__half2*)&r1.y);
        acc0.x += z0 * v00.x; acc0.y += z0 * v00.y;
        acc0.z += z0 * v01.x; acc0.w += z0 * v01.y;
        acc1.x += z1 * v10.x; acc1.y += z1 * v10.y;
        acc1.z += z1 * v11.x; acc1.w += z1 * v11.y;
    }
    if (j < cnt) {
        int s0 = j + half;                     // padded lanes carry z=0,c=0
        int   c0 = __shfl_sync(0xFFFFFFFFu, c, s0);
        float z0 = __shfl_sync(0xFFFFFFFFu, z, s0);
        uint2 r0 = *(const uint2*)(g_fts_h + (size_t)c0 * 32 + li * 2);
        float2 v00 = __half22float2(*(__half2*)&r0.x);
        float2 v01 = __half22float2(*(__half2*)&r0.y);
        acc0.x += z0 * v00.x; acc0.y += z0 * v00.y;
        acc0.z += z0 * v01.x; acc0.w += z0 * v01.y;
    }
}

__device__ __forceinline__ void finish_row(int row, int deg, int half, int li,
                                           float4 acc0, float4 acc1, float ssum,
                                           float* __restrict__ out) {
    float4 acc = make_float4(acc0.x + acc1.x, acc0.y + acc1.y,
                             acc0.z + acc1.z, acc0.w + acc1.w);
    acc.x += __shfl_xor_sync(0xFFFFFFFFu, acc.x, 16);
    acc.y += __shfl_xor_sync(0xFFFFFFFFu, acc.y, 16);
    acc.z += __shfl_xor_sync(0xFFFFFFFFu, acc.z, 16);
    acc.w += __shfl_xor_sync(0xFFFFFFFFu, acc.w, 16);
    #pragma unroll
    for (int o = 16; o; o >>= 1) ssum += __shfl_xor_sync(0xFFFFFFFFu, ssum, o);
    if (half == 0) {
        float inv = (deg > 0) ? (1.f / ssum) : 0.f;
        float4 o4 = make_float4(acc.x * inv, acc.y * inv, acc.z * inv, acc.w * inv);
        o4.x = o4.x > 0.f ? o4.x : expm1f(o4.x);
        o4.y = o4.y > 0.f ? o4.y : expm1f(o4.y);
        o4.z = o4.z > 0.f ? o4.z : expm1f(o4.z);
        o4.w = o4.w > 0.f ? o4.w : expm1f(o4.w);
        *(float4*)(out + (size_t)row * HID + li * 4) = o4;
    }
}

__global__ void __launch_bounds__(256)
attn_kernel(const int* __restrict__ ec, const float* __restrict__ ev,
            float* __restrict__ out, int N) {
    const int warp = threadIdx.x >> 5;
    const int lane = threadIdx.x & 31;
    int rowA = blockIdx.x * 16 + warp * 2;
    int rowB = rowA + 1;
    if (rowA >= N) return;
    const bool hasB = (rowB < N);

    int sA = g_rowptr[rowA], eA = g_rowptr[rowA + 1];
    int sB = 0, eB = 0;
    if (hasB) { sB = g_rowptr[rowB]; eB = g_rowptr[rowB + 1]; }
    float f1A = g_f1[rowA];
    float f1B = hasB ? g_f1[rowB] : 0.f;

    const int half = lane >> 4;
    const int li   = lane & 15;

    float4 aA0 = make_float4(0, 0, 0, 0), aA1 = make_float4(0, 0, 0, 0);
    float4 aB0 = make_float4(0, 0, 0, 0), aB1 = make_float4(0, 0, 0, 0);
    float ssA = 0.f, ssB = 0.f;

    int baseA = sA, baseB = sB;
    while (baseA < eA || baseB < eB) {
        // ---- z-phases (independent rows; loads overlap) ----
        float zA = 0.f; int cA = 0; int cntA = 0;
        if (baseA < eA) {
            cntA = min(32, eA - baseA);
            int idx = baseA + lane;
            if (idx < eA) {
                cA = ec[idx];
                float l = ev[idx] * (f1A + g_f2[cA]);
                l = fmaxf(l, LRELU_ALPHA * l);
                zA = __expf(l);
            }
            ssA += zA;
        }
        float zB = 0.f; int cB = 0; int cntB = 0;
        if (baseB < eB) {
            cntB = min(32, eB - baseB);
            int idx = baseB + lane;
            if (idx < eB) {
                cB = ec[idx];
                float l = ev[idx] * (f1B + g_f2[cB]);
                l = fmaxf(l, LRELU_ALPHA * l);
                zB = __expf(l);
            }
            ssB += zB;
        }
        // ---- gathers (independent; 4 loads in flight per step) ----
        if (cntA) gather_chunk(cntA, half, li, cA, zA, aA0, aA1);
        if (cntB) gather_chunk(cntB, half, li, cB, zB, aB0, aB1);
        baseA += 32;
        baseB += 32;
    }

    finish_row(rowA, eA - sA, half, li, aA0, aA1, ssA, out);
    if (hasB) finish_row(rowB, eB - sB, half, li, aB0, aB1, ssB, out);
}

// ============================================================================
// launch
// ============================================================================
extern "C" void kernel_launch(void* const* d_in, const int* in_sizes, int n_in,
                              void* d_out, int out_size) {
    const float* seq = (const float*)d_in[0];
    const int*   er  = (const int*)d_in[1];
    const int*   ec  = (const int*)d_in[2];
    const float* ev  = (const float*)d_in[3];
    const float* W   = (const float*)d_in[4];
    const float* a1  = (const float*)d_in[5];
    const float* b1  = (const float*)d_in[6];
    const float* a2  = (const float*)d_in[7];
    const float* b2  = (const float*)d_in[8];
    // d_in[9] = bias_zero (all zeros — no-op)
    float* out = (float*)d_out;

    int N = in_sizes[0] / FIN;   // seq is [1, N, 128]
    int E = in_sizes[1];

    const int SMEM = (FIN * HID + KSTAGE * XT_STRIDE) * (int)sizeof(float);  // ~65KB
    cudaFuncSetAttribute(gemm_f12_kernel,
                         cudaFuncAttributeMaxDynamicSharedMemorySize, SMEM);

    gemm_f12_kernel<<<(N + 127) / 128, 256, SMEM>>>(seq, W, a1, b1, a2, b2, N);
    build_rowptr<<<(E + 255) / 256, 256>>>(er, E, N);
    attn_kernel<<<(N + 15) / 16, 256>>>(ec, ev, out, N);
}

// round 17
// speedup vs baseline: 1.7091x; 1.0929x over previous
#include <cuda_runtime.h>
#include <cuda_fp16.h>
#include <math.h>
#include <stdint.h>

#define FIN 128
#define HID 64
#define N_MAX 100032
#define E_MAX 3200000
#define LRELU_ALPHA 0.2f

// ---- scratch (static device globals; no allocation allowed) ----
__device__ __half2 g_fts_h[(size_t)N_MAX * 32];  // seq@W as fp16 [N,64] 12.8MB (L2-resident)
__device__ float   g_f1[N_MAX];
__device__ float   g_f2[N_MAX];
__device__ float   g_z[E_MAX];                   // per-edge softmax numerators, 12.8MB
__device__ int     g_rowptr[N_MAX + 1];

#define XT_STRIDE 132   // floats per k-row of transposed X tile
#define KSTAGE    64    // k rows resident per stage

// ============================================================================
// K1: seq_fts = seq @ W via packed fma.rn.f32x2 (FFMA2) — measured-best R12
//   version (55.1us). Two-stage Xt -> 65KB smem -> 3 CTAs/SM.
//   Fused epilogue: f1/f2 dots + fp16 fts store.
// ============================================================================
__global__ void __launch_bounds__(256, 3)
gemm_f12_kernel(const float* __restrict__ seq, const float* __restrict__ W,
                const float* __restrict__ a1, const float* __restrict__ b1,
                const float* __restrict__ a2, const float* __restrict__ b2,
                int N) {
    extern __shared__ float sm[];
    float* Ws = sm;                       // [128][64]            32KB (full K)
    float* Xt = sm + FIN * HID;           // [64][132] transposed 33KB (half K)
    const int tid = threadIdx.x;
    const int n0 = blockIdx.x * 128;

    {
        const float4* W4 = (const float4*)W;
        float4* Ws4 = (float4*)Ws;
        #pragma unroll
        for (int i = tid; i < FIN * HID / 4; i += 256) Ws4[i] = W4[i];
    }

    const int tx = tid & 15;   // hid group: cols [tx*4, tx*4+4)
    const int ty = tid >> 4;   // node group: nodes [ty*8, ty*8+8) as 4 pairs

    unsigned bAddr = (unsigned)__cvta_generic_to_shared(Ws + tx * 4);
    unsigned aAddr = (unsigned)__cvta_generic_to_shared(Xt + ty * 8);

    unsigned long long acc[4][4];
    #pragma unroll
    for (int p = 0; p < 4; p++)
        #pragma unroll
        for (int h = 0; h < 4; h++) acc[p][h] = 0ull;

    for (int stage = 0; stage < 2; stage++) {
        __syncthreads();
        for (int i = tid; i < 128 * 16; i += 256) {
            int node = i & 127;
            int q = i >> 7;
            int kk4 = stage * 16 + q;
            float4 v = make_float4(0.f, 0.f, 0.f, 0.f);
            if (n0 + node < N)
                v = ((const float4*)(seq + (size_t)(n0 + node) * FIN))[kk4];
            Xt[(q * 4 + 0) * XT_STRIDE + node] = v.x;
            Xt[(q * 4 + 1) * XT_STRIDE + node] = v.y;
            Xt[(q * 4 + 2) * XT_STRIDE + node] = v.z;
            Xt[(q * 4 + 3) * XT_STRIDE + node] = v.w;
        }
        __syncthreads();

        const unsigned bBase = bAddr + (unsigned)(stage * KSTAGE * HID * 4);

        #pragma unroll 4
        for (int k = 0; k < KSTAGE; k++) {
            unsigned long long a01, a23, a45, a67;
            unsigned ak = aAddr + (unsigned)(k * (XT_STRIDE * 4));
            asm volatile("ld.shared.v2.u64 {%0,%1}, [%2];"
                         : "=l"(a01), "=l"(a23) : "r"(ak));
            asm volatile("ld.shared.v2.u64 {%0,%1}, [%2];"
                         : "=l"(a45), "=l"(a67) : "r"(ak + 16));
            float4 b;
            asm volatile("ld.shared.v4.f32 {%0,%1,%2,%3}, [%4];"
                         : "=f"(b.x), "=f"(b.y), "=f"(b.z), "=f"(b.w)
                         : "r"(bBase + (unsigned)(k * HID * 4)));
            unsigned long long bb0, bb1, bb2, bb3;
            asm("mov.b64 %0, {%1,%1};" : "=l"(bb0) : "f"(b.x));
            asm("mov.b64 %0, {%1,%1};" : "=l"(bb1) : "f"(b.y));
            asm("mov.b64 %0, {%1,%1};" : "=l"(bb2) : "f"(b.z));
            asm("mov.b64 %0, {%1,%1};" : "=l"(bb3) : "f"(b.w));
            asm("fma.rn.f32x2 %0,%1,%2,%0;" : "+l"(acc[0][0]) : "l"(a01), "l"(bb0));
            asm("fma.rn.f32x2 %0,%1,%2,%0;" : "+l"(acc[0][1]) : "l"(a01), "l"(bb1));
            asm("fma.rn.f32x2 %0,%1,%2,%0;" : "+l"(acc[0][2]) : "l"(a01), "l"(bb2));
            asm("fma.rn.f32x2 %0,%1,%2,%0;" : "+l"(acc[0][3]) : "l"(a01), "l"(bb3));
            asm("fma.rn.f32x2 %0,%1,%2,%0;" : "+l"(acc[1][0]) : "l"(a23), "l"(bb0));
            asm("fma.rn.f32x2 %0,%1,%2,%0;" : "+l"(acc[1][1]) : "l"(a23), "l"(bb1));
            asm("fma.rn.f32x2 %0,%1,%2,%0;" : "+l"(acc[1][2]) : "l"(a23), "l"(bb2));
            asm("fma.rn.f32x2 %0,%1,%2,%0;" : "+l"(acc[1][3]) : "l"(a23), "l"(bb3));
            asm("fma.rn.f32x2 %0,%1,%2,%0;" : "+l"(acc[2][0]) : "l"(a45), "l"(bb0));
            asm("fma.rn.f32x2 %0,%1,%2,%0;" : "+l"(acc[2][1]) : "l"(a45), "l"(bb1));
            asm("fma.rn.f32x2 %0,%1,%2,%0;" : "+l"(acc[2][2]) : "l"(a45), "l"(bb2));
            asm("fma.rn.f32x2 %0,%1,%2,%0;" : "+l"(acc[2][3]) : "l"(a45), "l"(bb3));
            asm("fma.rn.f32x2 %0,%1,%2,%0;" : "+l"(acc[3][0]) : "l"(a67), "l"(bb0));
            asm("fma.rn.f32x2 %0,%1,%2,%0;" : "+l"(acc[3][1]) : "l"(a67), "l"(bb1));
            asm("fma.rn.f32x2 %0,%1,%2,%0;" : "+l"(acc[3][2]) : "l"(a67), "l"(bb2));
            asm("fma.rn.f32x2 %0,%1,%2,%0;" : "+l"(acc[3][3]) : "l"(a67), "l"(bb3));
        }
    }

    float af[8][4];
    #pragma unroll
    for (int p = 0; p < 4; p++)
        #pragma unroll
        for (int h = 0; h < 4; h++)
            asm("mov.b64 {%0,%1}, %2;"
                : "=f"(af[2 * p][h]), "=f"(af[2 * p + 1][h]) : "l"(acc[p][h]));

    #pragma unroll
    for (int i = 0; i < 8; i++) {
        int n = n0 + ty * 8 + i;
        if (n < N) {
            __half2 h0 = __floats2half2_rn(af[i][0], af[i][1]);
            __half2 h1 = __floats2half2_rn(af[i][2], af[i][3]);
            __half2* dst = g_fts_h + (size_t)n * 32 + tx * 2;
            dst[0] = h0;
            dst[1] = h1;
        }
    }

    float a1v0 = a1[tx * 4], a1v1 = a1[tx * 4 + 1], a1v2 = a1[tx * 4 + 2], a1v3 = a1[tx * 4 + 3];
    float a2v0 = a2[tx * 4], a2v1 = a2[tx * 4 + 1], a2v2 = a2[tx * 4 + 2], a2v3 = a2[tx * 4 + 3];
    float bb1s = b1[0], bb2s = b2[0];
    #pragma unroll
    for (int i = 0; i < 8; i++) {
        float p1 = af[i][0] * a1v0 + af[i][1] * a1v1 + af[i][2] * a1v2 + af[i][3] * a1v3;
        float p2 = af[i][0] * a2v0 + af[i][1] * a2v1 + af[i][2] * a2v2 + af[i][3] * a2v3;
        #pragma unroll
        for (int o = 8; o; o >>= 1) {
            p1 += __shfl_xor_sync(0xFFFFFFFFu, p1, o);
            p2 += __shfl_xor_sync(0xFFFFFFFFu, p2, o);
        }
        int n = n0 + ty * 8 + i;
        if (tx == 0 && n < N) {
            g_f1[n] = p1 + bb1s;
            g_f2[n] = p2 + bb2s;
        }
    }
}

// ============================================================================
// K2: CSR row_ptr from sorted edge_row
// ============================================================================
__global__ void build_rowptr(const int* __restrict__ erow, int E, int N) {
    int e = blockIdx.x * blockDim.x + threadIdx.x;
    if (e >= E) return;
    int r = erow[e];
    int rp = (e == 0) ? -1 : erow[e - 1];
    for (int rr = rp + 1; rr <= r; ++rr) g_rowptr[rr] = e;
    if (e == E - 1)
        for (int rr = r + 1; rr <= N; ++rr) g_rowptr[rr] = E;
}

// ============================================================================
// K3: edge-parallel z: z[e] = exp(lrelu(ev*(f1[er]+f2[ec]))).
//   4 edges/thread vectorized — this pattern measured 19.5us in R2. It moves
//   the random f2 gather OUT of the attn critical loop to a streaming kernel
//   with maximal outstanding-miss parallelism.
// ============================================================================
__global__ void __launch_bounds__(256)
zlogits_kernel(const int* __restrict__ er, const int* __restrict__ ec,
               const float* __restrict__ ev, int E) {
    int base = (blockIdx.x * 256 + threadIdx.x) * 4;
    if (base >= E) return;
    if (base + 4 <= E) {
        int4   r4 = *(const int4*)(er + base);
        int4   c4 = *(const int4*)(ec + base);
        float4 v4 = *(const float4*)(ev + base);
        float f1a = g_f1[r4.x], f1b = g_f1[r4.y], f1c = g_f1[r4.z], f1d = g_f1[r4.w];
        float f2a = g_f2[c4.x], f2b = g_f2[c4.y], f2c = g_f2[c4.z], f2d = g_f2[c4.w];
        float la = v4.x * (f1a + f2a);
        float lb = v4.y * (f1b + f2b);
        float lc = v4.z * (f1c + f2c);
        float ld = v4.w * (f1d + f2d);
        la = fmaxf(la, LRELU_ALPHA * la);
        lb = fmaxf(lb, LRELU_ALPHA * lb);
        lc = fmaxf(lc, LRELU_ALPHA * lc);
        ld = fmaxf(ld, LRELU_ALPHA * ld);
        *(float4*)(g_z + base) =
            make_float4(__expf(la), __expf(lb), __expf(lc), __expf(ld));
    } else {
        for (int e = base; e < E; e++) {
            float l = ev[e] * (g_f1[er[e]] + g_f2[ec[e]]);
            l = fmaxf(l, LRELU_ALPHA * l);
            g_z[e] = __expf(l);
        }
    }
}

// ============================================================================
// K4: fused segmented softmax-normalize + SpMM + ELU. One warp per row —
//   R5's exact best-measured gather machinery, but z is now a COALESCED load
//   (no random f2 gather / exp on the critical path).
// ============================================================================
__global__ void __launch_bounds__(256)
attn_kernel(const int* __restrict__ ec, float* __restrict__ out, int N) {
    int row  = (blockIdx.x * 256 + threadIdx.x) >> 5;
    int lane = threadIdx.x & 31;
    if (row >= N) return;

    int s = g_rowptr[row];
    int e = g_rowptr[row + 1];

    const int half = lane >> 4;   // which edge of the pair this lane serves
    const int li   = lane & 15;   // 4-element slice (of 64) within the row

    float4 accA = make_float4(0.f, 0.f, 0.f, 0.f);
    float4 accB = make_float4(0.f, 0.f, 0.f, 0.f);
    float ssum = 0.f;

    for (int base = s; base < e; base += 32) {
        int idx = base + lane;
        float z = 0.f;
        int c = 0;
        if (idx < e) {
            c = ec[idx];
            z = g_z[idx];          // coalesced — the only new memory op
        }
        ssum += z;
        int cnt = min(32, e - base);

        int j = 0;
        for (; j + 2 < cnt; j += 4) {
            int sA = j + half;
            int sB = j + 2 + half;
            int   cA = __shfl_sync(0xFFFFFFFFu, c, sA);
            float zA = __shfl_sync(0xFFFFFFFFu, z, sA);
            int   cB = __shfl_sync(0xFFFFFFFFu, c, sB);
            float zB = __shfl_sync(0xFFFFFFFFu, z, sB);
            uint2 rA = *(const uint2*)(g_fts_h + (size_t)cA * 32 + li * 2);
            uint2 rB = *(const uint2*)(g_fts_h + (size_t)cB * 32 + li * 2);
            float2 vA0 = __half22float2(*(__half2*)&rA.x);
            float2 vA1 = __half22float2(*(__half2*)&rA.y);
            float2 vB0 = __half22float2(*(__half2*)&rB.x);
            float2 vB1 = __half22float2(*(__half2*)&rB.y);
            accA.x += zA * vA0.x; accA.y += zA * vA0.y;
            accA.z += zA * vA1.x; accA.w += zA * vA1.y;
            accB.x += zB * vB0.x; accB.y += zB * vB0.y;
            accB.z += zB * vB1.x; accB.w += zB * vB1.y;
        }
        if (j < cnt) {
            int sA = j + half;                  // padded lanes carry z=0, c=0
            int   cA = __shfl_sync(0xFFFFFFFFu, c, sA);
            float zA = __shfl_sync(0xFFFFFFFFu, z, sA);
            uint2 rA = *(const uint2*)(g_fts_h + (size_t)cA * 32 + li * 2);
            float2 vA0 = __half22float2(*(__half2*)&rA.x);
            float2 vA1 = __half22float2(*(__half2*)&rA.y);
            accA.x += zA * vA0.x; accA.y += zA * vA0.y;
            accA.z += zA * vA1.x; accA.w += zA * vA1.y;
        }
    }

    float4 acc = make_float4(accA.x + accB.x, accA.y + accB.y,
                             accA.z + accB.z, accA.w + accB.w);
    acc.x += __shfl_xor_sync(0xFFFFFFFFu, acc.x, 16);
    acc.y += __shfl_xor_sync(0xFFFFFFFFu, acc.y, 16);
    acc.z += __shfl_xor_sync(0xFFFFFFFFu, acc.z, 16);
    acc.w += __shfl_xor_sync(0xFFFFFFFFu, acc.w, 16);
    #pragma unroll
    for (int o = 16; o; o >>= 1) ssum += __shfl_xor_sync(0xFFFFFFFFu, ssum, o);

    if (half == 0) {
        float4 o4 = make_float4(0.f, 0.f, 0.f, 0.f);
        if (e > s) {
            float inv = 1.f / ssum;
            o4 = make_float4(acc.x * inv, acc.y * inv, acc.z * inv, acc.w * inv);
        }
        o4.x = o4.x > 0.f ? o4.x : expm1f(o4.x);
        o4.y = o4.y > 0.f ? o4.y : expm1f(o4.y);
        o4.z = o4.z > 0.f ? o4.z : expm1f(o4.z);
        o4.w = o4.w > 0.f ? o4.w : expm1f(o4.w);
        *(float4*)(out + (size_t)row * HID + li * 4) = o4;
    }
}

// ============================================================================
// launch
// ============================================================================
extern "C" void kernel_launch(void* const* d_in, const int* in_sizes, int n_in,
                              void* d_out, int out_size) {
    const float* seq = (const float*)d_in[0];
    const int*   er  = (const int*)d_in[1];
    const int*   ec  = (const int*)d_in[2];
    const float* ev  = (const float*)d_in[3];
    const float* W   = (const float*)d_in[4];
    const float* a1  = (const float*)d_in[5];
    const float* b1  = (const float*)d_in[6];
    const float* a2  = (const float*)d_in[7];
    const float* b2  = (const float*)d_in[8];
    // d_in[9] = bias_zero (all zeros — no-op)
    float* out = (float*)d_out;

    int N = in_sizes[0] / FIN;   // seq is [1, N, 128]
    int E = in_sizes[1];

    const int SMEM = (FIN * HID + KSTAGE * XT_STRIDE) * (int)sizeof(float);  // ~65KB
    cudaFuncSetAttribute(gemm_f12_kernel,
                         cudaFuncAttributeMaxDynamicSharedMemorySize, SMEM);

    gemm_f12_kernel<<<(N + 127) / 128, 256, SMEM>>>(seq, W, a1, b1, a2, b2, N);
    build_rowptr<<<(E + 255) / 256, 256>>>(er, E, N);
    zlogits_kernel<<<(E + 1023) / 1024, 256>>>(er, ec, ev, E);
    attn_kernel<<<(N + 7) / 8, 256>>>(ec, out, N);
}